// round 1
// baseline (speedup 1.0000x reference)
#include <cuda_runtime.h>
#include <cuda_bf16.h>

#define EPS_NORM 1e-8f
#define CLAMP_MIN 1e-12f
#define CLAMP_MAX 1e12f

__global__ void zero_out_kernel(float* out) {
    out[0] = 0.0f;
}

// One warp per row. D=256 f32 = 64 float4 = 2 float4 per lane.
__global__ __launch_bounds__(1024, 2)
void inner_cos_kernel(const float* __restrict__ ref_emb,
                      const int*   __restrict__ ref_label,
                      const float* __restrict__ centers,
                      float* __restrict__ out,
                      int N, float inv_n) {
    const int gwarp = (blockIdx.x * blockDim.x + threadIdx.x) >> 5;
    const int lane  = threadIdx.x & 31;
    const int wid   = threadIdx.x >> 5;

    __shared__ float ssum[32];

    float row_val = 0.0f;
    if (gwarp < N) {
        const int lab = __ldg(&ref_label[gwarp]);  // broadcast within warp
        const float4* __restrict__ xr = reinterpret_cast<const float4*>(ref_emb) + (size_t)gwarp * 64;
        const float4* __restrict__ cr = reinterpret_cast<const float4*>(centers) + (size_t)lab * 64;

        float dot = 0.0f, nx2 = 0.0f, nc2 = 0.0f;
        #pragma unroll
        for (int j = 0; j < 2; ++j) {
            float4 a = xr[j * 32 + lane];
            float4 b = cr[j * 32 + lane];
            dot = fmaf(a.x, b.x, dot); dot = fmaf(a.y, b.y, dot);
            dot = fmaf(a.z, b.z, dot); dot = fmaf(a.w, b.w, dot);
            nx2 = fmaf(a.x, a.x, nx2); nx2 = fmaf(a.y, a.y, nx2);
            nx2 = fmaf(a.z, a.z, nx2); nx2 = fmaf(a.w, a.w, nx2);
            nc2 = fmaf(b.x, b.x, nc2); nc2 = fmaf(b.y, b.y, nc2);
            nc2 = fmaf(b.z, b.z, nc2); nc2 = fmaf(b.w, b.w, nc2);
        }

        #pragma unroll
        for (int off = 16; off > 0; off >>= 1) {
            dot += __shfl_down_sync(0xFFFFFFFFu, dot, off);
            nx2 += __shfl_down_sync(0xFFFFFFFFu, nx2, off);
            nc2 += __shfl_down_sync(0xFFFFFFFFu, nc2, off);
        }

        if (lane == 0) {
            float denom = fmaxf(sqrtf(nx2) * sqrtf(nc2), EPS_NORM);
            float cd = 1.0f - dot / denom;
            cd = fminf(fmaxf(cd, CLAMP_MIN), CLAMP_MAX);
            row_val = cd;
        }
    }

    // Block reduction over warps (32 warps/block)
    if (lane == 0) ssum[wid] = row_val;
    __syncthreads();

    if (wid == 0) {
        float v = (lane < (blockDim.x >> 5)) ? ssum[lane] : 0.0f;
        #pragma unroll
        for (int off = 16; off > 0; off >>= 1)
            v += __shfl_down_sync(0xFFFFFFFFu, v, off);
        if (lane == 0)
            atomicAdd(out, v * inv_n);
    }
}

extern "C" void kernel_launch(void* const* d_in, const int* in_sizes, int n_in,
                              void* d_out, int out_size) {
    const float* ref_emb   = (const float*)d_in[0];
    const int*   ref_label = (const int*)d_in[1];
    const float* centers   = (const float*)d_in[2];
    float* out = (float*)d_out;

    const int N = in_sizes[1];          // 262144 labels
    const float inv_n = 1.0f / (float)N;

    zero_out_kernel<<<1, 1>>>(out);

    const int threads = 1024;           // 32 warps = 32 rows per block
    const int rows_per_block = threads / 32;
    const int blocks = (N + rows_per_block - 1) / rows_per_block;
    inner_cos_kernel<<<blocks, threads>>>(ref_emb, ref_label, centers, out, N, inv_n);
}

// round 2
// speedup vs baseline: 1.4832x; 1.4832x over previous
#include <cuda_runtime.h>
#include <cuda_bf16.h>

#define EPS_NORM 1e-8f
#define CLAMP_MIN 1e-12f
#define CLAMP_MAX 1e12f

__global__ void zero_out_kernel(float* out) {
    out[0] = 0.0f;
}

// Persistent grid: one wave, warp-per-row grid-stride loop.
// D=256 f32 = 64 float4 = 2 float4 per lane per row.
__global__ __launch_bounds__(1024, 2)
void inner_cos_kernel(const float* __restrict__ ref_emb,
                      const int*   __restrict__ ref_label,
                      const float* __restrict__ centers,
                      float* __restrict__ out,
                      int N, float inv_n) {
    const int lane = threadIdx.x & 31;
    const int wid  = threadIdx.x >> 5;
    const int warps_per_block = blockDim.x >> 5;
    const int gwarp0 = blockIdx.x * warps_per_block + wid;
    const int total_warps = gridDim.x * warps_per_block;

    __shared__ float ssum[32];

    float warp_acc = 0.0f;   // valid on lane 0

    for (int row = gwarp0; row < N; row += total_warps) {
        const int lab = __ldg(&ref_label[row]);
        const float4* __restrict__ xr = reinterpret_cast<const float4*>(ref_emb) + (size_t)row * 64;
        const float4* __restrict__ cr = reinterpret_cast<const float4*>(centers) + (size_t)lab * 64;

        // streaming (evict-first) loads for the big one-pass tensor
        float4 a0 = __ldcs(&xr[lane]);
        float4 a1 = __ldcs(&xr[32 + lane]);
        float4 b0 = __ldg(&cr[lane]);
        float4 b1 = __ldg(&cr[32 + lane]);

        float dot = 0.0f, nx2 = 0.0f, nc2 = 0.0f;
        dot = fmaf(a0.x, b0.x, dot); dot = fmaf(a0.y, b0.y, dot);
        dot = fmaf(a0.z, b0.z, dot); dot = fmaf(a0.w, b0.w, dot);
        dot = fmaf(a1.x, b1.x, dot); dot = fmaf(a1.y, b1.y, dot);
        dot = fmaf(a1.z, b1.z, dot); dot = fmaf(a1.w, b1.w, dot);
        nx2 = fmaf(a0.x, a0.x, nx2); nx2 = fmaf(a0.y, a0.y, nx2);
        nx2 = fmaf(a0.z, a0.z, nx2); nx2 = fmaf(a0.w, a0.w, nx2);
        nx2 = fmaf(a1.x, a1.x, nx2); nx2 = fmaf(a1.y, a1.y, nx2);
        nx2 = fmaf(a1.z, a1.z, nx2); nx2 = fmaf(a1.w, a1.w, nx2);
        nc2 = fmaf(b0.x, b0.x, nc2); nc2 = fmaf(b0.y, b0.y, nc2);
        nc2 = fmaf(b0.z, b0.z, nc2); nc2 = fmaf(b0.w, b0.w, nc2);
        nc2 = fmaf(b1.x, b1.x, nc2); nc2 = fmaf(b1.y, b1.y, nc2);
        nc2 = fmaf(b1.z, b1.z, nc2); nc2 = fmaf(b1.w, b1.w, nc2);

        #pragma unroll
        for (int off = 16; off > 0; off >>= 1) {
            dot += __shfl_down_sync(0xFFFFFFFFu, dot, off);
            nx2 += __shfl_down_sync(0xFFFFFFFFu, nx2, off);
            nc2 += __shfl_down_sync(0xFFFFFFFFu, nc2, off);
        }

        if (lane == 0) {
            float denom = fmaxf(sqrtf(nx2) * sqrtf(nc2), EPS_NORM);
            float cd = 1.0f - dot / denom;
            cd = fminf(fmaxf(cd, CLAMP_MIN), CLAMP_MAX);
            warp_acc += cd;
        }
    }

    // One block-level reduction at the very end.
    if (lane == 0) ssum[wid] = warp_acc;
    __syncthreads();

    if (wid == 0) {
        float v = (lane < warps_per_block) ? ssum[lane] : 0.0f;
        #pragma unroll
        for (int off = 16; off > 0; off >>= 1)
            v += __shfl_down_sync(0xFFFFFFFFu, v, off);
        if (lane == 0)
            atomicAdd(out, v * inv_n);
    }
}

extern "C" void kernel_launch(void* const* d_in, const int* in_sizes, int n_in,
                              void* d_out, int out_size) {
    const float* ref_emb   = (const float*)d_in[0];
    const int*   ref_label = (const int*)d_in[1];
    const float* centers   = (const float*)d_in[2];
    float* out = (float*)d_out;

    const int N = in_sizes[1];          // 262144 labels
    const float inv_n = 1.0f / (float)N;

    zero_out_kernel<<<1, 1>>>(out);

    // One wave: 148 SMs x 2 blocks/SM (1024 thr, 30 regs -> 2048 thr/SM).
    const int threads = 1024;
    const int blocks  = 148 * 2;
    inner_cos_kernel<<<blocks, threads>>>(ref_emb, ref_label, centers, out, N, inv_n);
}

// round 3
// speedup vs baseline: 1.4884x; 1.0035x over previous
#include <cuda_runtime.h>
#include <cuda_bf16.h>

#define EPS_NORM 1e-8f
#define CLAMP_MIN 1e-12f
#define CLAMP_MAX 1e12f

// Pre-normalized centers scratch (C <= 256, D = 256)
__device__ float g_cnorm[256 * 256];

// Prep: zero the output and write normalized centers (one warp per center row).
__global__ void prep_kernel(const float* __restrict__ centers, float* __restrict__ out, int C) {
    if (blockIdx.x == 0 && threadIdx.x == 0) out[0] = 0.0f;

    const int warp = (blockIdx.x * blockDim.x + threadIdx.x) >> 5;
    const int lane = threadIdx.x & 31;
    if (warp >= C) return;

    const float4* __restrict__ cr = reinterpret_cast<const float4*>(centers) + (size_t)warp * 64;
    float4 b0 = cr[lane];
    float4 b1 = cr[32 + lane];

    float s = 0.0f;
    s = fmaf(b0.x, b0.x, s); s = fmaf(b0.y, b0.y, s);
    s = fmaf(b0.z, b0.z, s); s = fmaf(b0.w, b0.w, s);
    s = fmaf(b1.x, b1.x, s); s = fmaf(b1.y, b1.y, s);
    s = fmaf(b1.z, b1.z, s); s = fmaf(b1.w, b1.w, s);

    #pragma unroll
    for (int off = 16; off > 0; off >>= 1)
        s += __shfl_xor_sync(0xFFFFFFFFu, s, off);

    const float inv = rsqrtf(fmaxf(s, 1e-24f));
    b0.x *= inv; b0.y *= inv; b0.z *= inv; b0.w *= inv;
    b1.x *= inv; b1.y *= inv; b1.z *= inv; b1.w *= inv;

    float4* __restrict__ dst = reinterpret_cast<float4*>(g_cnorm) + (size_t)warp * 64;
    dst[lane]      = b0;
    dst[32 + lane] = b1;
}

// Main: persistent grid, 2 rows per warp per iteration, split-butterfly reduce.
__global__ __launch_bounds__(512, 2)
void inner_cos_kernel(const float* __restrict__ ref_emb,
                      const int*   __restrict__ ref_label,
                      float* __restrict__ out,
                      int N, float inv_n) {
    const int lane = threadIdx.x & 31;
    const int wid  = threadIdx.x >> 5;
    const int warps_per_block = blockDim.x >> 5;
    const int gwarp = blockIdx.x * warps_per_block + wid;
    const int total_warps = gridDim.x * warps_per_block;

    __shared__ float ssum[16];

    const int Neven = N & ~1;
    float acc = 0.0f;   // meaningful on lanes 0 and 16

    for (int r = gwarp * 2; r < Neven; r += total_warps * 2) {
        const int lab0 = __ldg(&ref_label[r]);
        const int lab1 = __ldg(&ref_label[r + 1]);

        const float4* __restrict__ x0 = reinterpret_cast<const float4*>(ref_emb) + (size_t)r * 64;
        const float4* __restrict__ x1 = x0 + 64;
        const float4* __restrict__ c0 = reinterpret_cast<const float4*>(g_cnorm) + (size_t)lab0 * 64;
        const float4* __restrict__ c1 = reinterpret_cast<const float4*>(g_cnorm) + (size_t)lab1 * 64;

        // issue all 8 vector loads up front for MLP
        float4 a00 = __ldcs(&x0[lane]);
        float4 a01 = __ldcs(&x0[32 + lane]);
        float4 a10 = __ldcs(&x1[lane]);
        float4 a11 = __ldcs(&x1[32 + lane]);
        float4 b00 = __ldg(&c0[lane]);
        float4 b01 = __ldg(&c0[32 + lane]);
        float4 b10 = __ldg(&c1[lane]);
        float4 b11 = __ldg(&c1[32 + lane]);

        float dot0 = 0.f, nx0 = 0.f, dot1 = 0.f, nx1 = 0.f;
        dot0 = fmaf(a00.x, b00.x, dot0); dot0 = fmaf(a00.y, b00.y, dot0);
        dot0 = fmaf(a00.z, b00.z, dot0); dot0 = fmaf(a00.w, b00.w, dot0);
        dot0 = fmaf(a01.x, b01.x, dot0); dot0 = fmaf(a01.y, b01.y, dot0);
        dot0 = fmaf(a01.z, b01.z, dot0); dot0 = fmaf(a01.w, b01.w, dot0);
        nx0  = fmaf(a00.x, a00.x, nx0);  nx0  = fmaf(a00.y, a00.y, nx0);
        nx0  = fmaf(a00.z, a00.z, nx0);  nx0  = fmaf(a00.w, a00.w, nx0);
        nx0  = fmaf(a01.x, a01.x, nx0);  nx0  = fmaf(a01.y, a01.y, nx0);
        nx0  = fmaf(a01.z, a01.z, nx0);  nx0  = fmaf(a01.w, a01.w, nx0);
        dot1 = fmaf(a10.x, b10.x, dot1); dot1 = fmaf(a10.y, b10.y, dot1);
        dot1 = fmaf(a10.z, b10.z, dot1); dot1 = fmaf(a10.w, b10.w, dot1);
        dot1 = fmaf(a11.x, b11.x, dot1); dot1 = fmaf(a11.y, b11.y, dot1);
        dot1 = fmaf(a11.z, b11.z, dot1); dot1 = fmaf(a11.w, b11.w, dot1);
        nx1  = fmaf(a10.x, a10.x, nx1);  nx1  = fmaf(a10.y, a10.y, nx1);
        nx1  = fmaf(a10.z, a10.z, nx1);  nx1  = fmaf(a10.w, a10.w, nx1);
        nx1  = fmaf(a11.x, a11.x, nx1);  nx1  = fmaf(a11.y, a11.y, nx1);
        nx1  = fmaf(a11.z, a11.z, nx1);  nx1  = fmaf(a11.w, a11.w, nx1);

        // Split-butterfly reduction: 2 xor-levels on all 4 values...
        dot0 += __shfl_xor_sync(0xFFFFFFFFu, dot0, 16);
        dot0 += __shfl_xor_sync(0xFFFFFFFFu, dot0, 8);
        nx0  += __shfl_xor_sync(0xFFFFFFFFu, nx0, 16);
        nx0  += __shfl_xor_sync(0xFFFFFFFFu, nx0, 8);
        dot1 += __shfl_xor_sync(0xFFFFFFFFu, dot1, 16);
        dot1 += __shfl_xor_sync(0xFFFFFFFFu, dot1, 8);
        nx1  += __shfl_xor_sync(0xFFFFFFFFu, nx1, 16);
        nx1  += __shfl_xor_sync(0xFFFFFFFFu, nx1, 8);

        // ...then each 8-lane group finishes one value.
        const int g = lane >> 3;
        float w = (g == 0) ? dot0 : (g == 1) ? nx0 : (g == 2) ? dot1 : nx1;
        w += __shfl_xor_sync(0xFFFFFFFFu, w, 4);
        w += __shfl_xor_sync(0xFFFFFFFFu, w, 2);
        w += __shfl_xor_sync(0xFFFFFFFFu, w, 1);
        const float other = __shfl_xor_sync(0xFFFFFFFFu, w, 8);  // lane0<-nx0, lane16<-nx1

        if ((lane & 15) == 0) {
            // centers prenormalized: cos = dot_hat / ||x||
            float cosv = w * rsqrtf(fmaxf(other, 1e-16f));
            float cd = 1.0f - cosv;
            cd = fminf(fmaxf(cd, CLAMP_MIN), CLAMP_MAX);
            acc += cd;
        }
    }

    // Odd-N tail (single row), handled by warp 0.
    if ((N & 1) && gwarp == 0) {
        const int r = N - 1;
        const int lab = __ldg(&ref_label[r]);
        const float4* __restrict__ xr = reinterpret_cast<const float4*>(ref_emb) + (size_t)r * 64;
        const float4* __restrict__ cr = reinterpret_cast<const float4*>(g_cnorm) + (size_t)lab * 64;
        float4 a0 = xr[lane], a1 = xr[32 + lane];
        float4 b0 = cr[lane], b1 = cr[32 + lane];
        float dot = 0.f, nx2 = 0.f;
        dot = fmaf(a0.x,b0.x,dot); dot = fmaf(a0.y,b0.y,dot);
        dot = fmaf(a0.z,b0.z,dot); dot = fmaf(a0.w,b0.w,dot);
        dot = fmaf(a1.x,b1.x,dot); dot = fmaf(a1.y,b1.y,dot);
        dot = fmaf(a1.z,b1.z,dot); dot = fmaf(a1.w,b1.w,dot);
        nx2 = fmaf(a0.x,a0.x,nx2); nx2 = fmaf(a0.y,a0.y,nx2);
        nx2 = fmaf(a0.z,a0.z,nx2); nx2 = fmaf(a0.w,a0.w,nx2);
        nx2 = fmaf(a1.x,a1.x,nx2); nx2 = fmaf(a1.y,a1.y,nx2);
        nx2 = fmaf(a1.z,a1.z,nx2); nx2 = fmaf(a1.w,a1.w,nx2);
        #pragma unroll
        for (int off = 16; off > 0; off >>= 1) {
            dot += __shfl_xor_sync(0xFFFFFFFFu, dot, off);
            nx2 += __shfl_xor_sync(0xFFFFFFFFu, nx2, off);
        }
        if (lane == 0) {
            float cosv = dot * rsqrtf(fmaxf(nx2, 1e-16f));
            float cd = 1.0f - cosv;
            acc += fminf(fmaxf(cd, CLAMP_MIN), CLAMP_MAX);
        }
    }

    // combine lane16 contribution into lane0
    acc += __shfl_xor_sync(0xFFFFFFFFu, acc, 16);
    if (lane == 0) ssum[wid] = acc;
    __syncthreads();

    if (wid == 0) {
        float v = (lane < warps_per_block) ? ssum[lane] : 0.0f;
        #pragma unroll
        for (int off = 8; off > 0; off >>= 1)
            v += __shfl_xor_sync(0xFFFFFFFFu, v, off);
        if (lane == 0)
            atomicAdd(out, v * inv_n);
    }
}

extern "C" void kernel_launch(void* const* d_in, const int* in_sizes, int n_in,
                              void* d_out, int out_size) {
    const float* ref_emb   = (const float*)d_in[0];
    const int*   ref_label = (const int*)d_in[1];
    const float* centers   = (const float*)d_in[2];
    float* out = (float*)d_out;

    const int N = in_sizes[1];
    const int C = in_sizes[2] / 256;     // D = 256
    const float inv_n = 1.0f / (float)N;

    // prep: zero out + normalize centers (warp per center)
    const int prep_threads = 512;
    const int prep_blocks = (C * 32 + prep_threads - 1) / prep_threads;
    prep_kernel<<<prep_blocks, prep_threads>>>(centers, out, C);

    const int threads = 512;             // 16 warps
    const int blocks  = 148 * 2;         // persistent single wave
    inner_cos_kernel<<<blocks, threads>>>(ref_emb, ref_label, out, N, inv_n);
}

// round 4
// speedup vs baseline: 1.5585x; 1.0471x over previous
#include <cuda_runtime.h>
#include <cuda_bf16.h>

#define CLAMP_MIN 1e-12f
#define CLAMP_MAX 1e12f

// Pre-normalized centers scratch (C <= 256, D = 256)
__device__ float g_cnorm[256 * 256];

// Prep: zero the output and write normalized centers (one warp per center row).
__global__ void prep_kernel(const float* __restrict__ centers, float* __restrict__ out, int C) {
    if (blockIdx.x == 0 && threadIdx.x == 0) out[0] = 0.0f;

    const int warp = (blockIdx.x * blockDim.x + threadIdx.x) >> 5;
    const int lane = threadIdx.x & 31;
    if (warp >= C) return;

    const float4* __restrict__ cr = reinterpret_cast<const float4*>(centers) + (size_t)warp * 64;
    float4 b0 = cr[lane];
    float4 b1 = cr[32 + lane];

    float s = 0.0f;
    s = fmaf(b0.x, b0.x, s); s = fmaf(b0.y, b0.y, s);
    s = fmaf(b0.z, b0.z, s); s = fmaf(b0.w, b0.w, s);
    s = fmaf(b1.x, b1.x, s); s = fmaf(b1.y, b1.y, s);
    s = fmaf(b1.z, b1.z, s); s = fmaf(b1.w, b1.w, s);

    #pragma unroll
    for (int off = 16; off > 0; off >>= 1)
        s += __shfl_xor_sync(0xFFFFFFFFu, s, off);

    const float inv = rsqrtf(fmaxf(s, 1e-24f));
    b0.x *= inv; b0.y *= inv; b0.z *= inv; b0.w *= inv;
    b1.x *= inv; b1.y *= inv; b1.z *= inv; b1.w *= inv;

    float4* __restrict__ dst = reinterpret_cast<float4*>(g_cnorm) + (size_t)warp * 64;
    dst[lane]      = b0;
    dst[32 + lane] = b1;
}

// Main: persistent grid, 1 row per warp per iter, lean 2-value split reduction.
// Target: <= 32 regs so 2x1024-thread blocks (64 warps) fit per SM.
__global__ __launch_bounds__(1024, 2)
void inner_cos_kernel(const float* __restrict__ ref_emb,
                      const int*   __restrict__ ref_label,
                      float* __restrict__ out,
                      int N, float inv_n) {
    const int lane = threadIdx.x & 31;
    const int wid  = threadIdx.x >> 5;
    const int warps_per_block = blockDim.x >> 5;
    const int gwarp = blockIdx.x * warps_per_block + wid;
    const int total_warps = gridDim.x * warps_per_block;

    __shared__ float ssum[32];

    float acc = 0.0f;   // meaningful on lane 0

    for (int row = gwarp; row < N; row += total_warps) {
        const int lab = __ldg(&ref_label[row]);
        const float4* __restrict__ xr = reinterpret_cast<const float4*>(ref_emb) + (size_t)row * 64;
        const float4* __restrict__ cr = reinterpret_cast<const float4*>(g_cnorm) + (size_t)lab * 64;

        float4 a0 = __ldcs(&xr[lane]);
        float4 a1 = __ldcs(&xr[32 + lane]);
        float4 b0 = __ldg(&cr[lane]);
        float4 b1 = __ldg(&cr[32 + lane]);

        float dot = 0.0f, nx2 = 0.0f;
        dot = fmaf(a0.x, b0.x, dot); dot = fmaf(a0.y, b0.y, dot);
        dot = fmaf(a0.z, b0.z, dot); dot = fmaf(a0.w, b0.w, dot);
        dot = fmaf(a1.x, b1.x, dot); dot = fmaf(a1.y, b1.y, dot);
        dot = fmaf(a1.z, b1.z, dot); dot = fmaf(a1.w, b1.w, dot);
        nx2 = fmaf(a0.x, a0.x, nx2); nx2 = fmaf(a0.y, a0.y, nx2);
        nx2 = fmaf(a0.z, a0.z, nx2); nx2 = fmaf(a0.w, a0.w, nx2);
        nx2 = fmaf(a1.x, a1.x, nx2); nx2 = fmaf(a1.y, a1.y, nx2);
        nx2 = fmaf(a1.z, a1.z, nx2); nx2 = fmaf(a1.w, a1.w, nx2);

        // Split reduction: one xor-16 level on both values, then
        // half-warps each finish one value over 16 lanes.
        dot += __shfl_xor_sync(0xFFFFFFFFu, dot, 16);
        nx2 += __shfl_xor_sync(0xFFFFFFFFu, nx2, 16);

        float w = (lane < 16) ? dot : nx2;
        w += __shfl_xor_sync(0xFFFFFFFFu, w, 8);
        w += __shfl_xor_sync(0xFFFFFFFFu, w, 4);
        w += __shfl_xor_sync(0xFFFFFFFFu, w, 2);
        w += __shfl_xor_sync(0xFFFFFFFFu, w, 1);
        const float nxv = __shfl_xor_sync(0xFFFFFFFFu, w, 16);  // lane0 <- nx sum

        if (lane == 0) {
            // centers prenormalized: cos = dot_hat / ||x||
            float cd = 1.0f - w * rsqrtf(fmaxf(nxv, 1e-16f));
            cd = fminf(fmaxf(cd, CLAMP_MIN), CLAMP_MAX);
            acc += cd;
        }
    }

    if (lane == 0) ssum[wid] = acc;
    __syncthreads();

    if (wid == 0) {
        float v = (lane < warps_per_block) ? ssum[lane] : 0.0f;
        #pragma unroll
        for (int off = 16; off > 0; off >>= 1)
            v += __shfl_xor_sync(0xFFFFFFFFu, v, off);
        if (lane == 0)
            atomicAdd(out, v * inv_n);
    }
}

extern "C" void kernel_launch(void* const* d_in, const int* in_sizes, int n_in,
                              void* d_out, int out_size) {
    const float* ref_emb   = (const float*)d_in[0];
    const int*   ref_label = (const int*)d_in[1];
    const float* centers   = (const float*)d_in[2];
    float* out = (float*)d_out;

    const int N = in_sizes[1];
    const int C = in_sizes[2] / 256;     // D = 256
    const float inv_n = 1.0f / (float)N;

    const int prep_threads = 512;
    const int prep_blocks = (C * 32 + prep_threads - 1) / prep_threads;
    prep_kernel<<<prep_blocks, prep_threads>>>(centers, out, C);

    const int threads = 1024;            // 32 warps/block
    const int blocks  = 148 * 2;         // persistent single wave, 64 warps/SM
    inner_cos_kernel<<<blocks, threads>>>(ref_emb, ref_label, out, N, inv_n);
}